// round 14
// baseline (speedup 1.0000x reference)
#include <cuda_runtime.h>
#include <cuda_fp16.h>
#include <cstdint>
#include <cstddef>

#define N_NODES 50000
#define N_EDGES 800000
#define SCAN_NB ((N_NODES + 255) / 256)   // 196 blocks
#define GEMM_MB ((N_NODES + 127) / 128)   // 391 CTAs in M
#define XCONV_ITEMS (N_NODES * 32)
#define DEG_NB ((N_EDGES + 255) / 256)    // 3125 blocks
#define PREP_ITEMS (XCONV_ITEMS + 2 * 256 * 256 + 512)
#define PREP_NB ((PREP_ITEMS + 255) / 256)

// ---- device scratch ----
// A1: fp16 [M,256] packed as uints (row stride 128 uints)
// layout: uints 0..63 = mean part (128 fp16), uints 64..127 = x part
__device__ __align__(16) unsigned g_A1[(size_t)N_NODES * 128];
__device__ __align__(16) unsigned g_A2[(size_t)N_NODES * 128];   // h fp16
__device__ __align__(16) __half   g_p[(size_t)N_NODES * 128];    // p fp16
__device__ __align__(16) __half   g_q[(size_t)N_NODES * 128];    // q fp16
__device__ __align__(16) unsigned short g_W1[256 * 256];         // fp16
__device__ __align__(16) unsigned short g_W2[256 * 256];         // fp16
__device__ __align__(16) float g_b1[256];
__device__ __align__(16) float g_b2[256];
__device__ __align__(16) float g_dinv[N_NODES];
__device__ __align__(16) int   g_degi[N_NODES];
__device__ __align__(16) int   g_row[N_NODES + 1];
__device__ __align__(16) int   g_cur[N_NODES];
__device__ __align__(16) int   g_csrc[N_EDGES];
__device__ __align__(16) unsigned g_look[SCAN_NB];               // lookback: status<<30|sum
__device__ int g_fmt;

// ---------------- helpers ----------------
__device__ __forceinline__ unsigned su32(const void* p) {
    return (unsigned)__cvta_generic_to_shared(p);
}

__device__ __forceinline__ int eidx_at(const void* ei, int fmt, int i) {
    return fmt ? (int)((const long long*)ei)[i] : ((const int*)ei)[i];
}

// ---------------------------------------------------------------
// init: zero degrees + lookback status + parallel format probe
// ---------------------------------------------------------------
__global__ void init_kernel(const int* __restrict__ ei32) {
    int i = blockIdx.x * blockDim.x + threadIdx.x;
    if (i < N_NODES) g_degi[i] = 0;
    if (i < SCAN_NB) g_look[i] = 0;
    if (blockIdx.x == 0) {
        __shared__ int s_nz;
        if (threadIdx.x == 0) s_nz = 0;
        __syncthreads();
        int nz = 0;
        for (int k = threadIdx.x; k < 512; k += 256)
            nz |= (ei32[2 * k + 1] != 0);
        if (nz) atomicOr(&s_nz, 1);
        __syncthreads();
        if (threadIdx.x == 0) g_fmt = s_nz ? 0 : 1;
    }
}

// ---------------------------------------------------------------
// fused: degree count (blocks < DEG_NB) + prep (remaining blocks)
// ---------------------------------------------------------------
__global__ void degprep_kernel(const void* __restrict__ ei,
                               const float* __restrict__ x,
                               const float* __restrict__ Wl1, const float* __restrict__ Wr1,
                               const float* __restrict__ Wl2, const float* __restrict__ Wr2,
                               const float* __restrict__ bl1, const float* __restrict__ bl2) {
    int b = blockIdx.x;
    if (b < DEG_NB) {
        int e = b * 256 + threadIdx.x;
        if (e < N_EDGES) {
            int d = eidx_at(ei, g_fmt, N_EDGES + e);
            atomicAdd(&g_degi[d], 1);
        }
        return;
    }
    int i = (b - DEG_NB) * 256 + threadIdx.x;
    if (i < XCONV_ITEMS) {
        int m = i >> 5, c4 = i & 31;
        float4 v = ((const float4*)x)[i];
        __half2 p0 = __floats2half2_rn(v.x, v.y);
        __half2 p1 = __floats2half2_rn(v.z, v.w);
        size_t base = (size_t)m * 128 + 64 + c4 * 2;
        g_A1[base]     = *reinterpret_cast<unsigned*>(&p0);
        g_A1[base + 1] = *reinterpret_cast<unsigned*>(&p1);
        return;
    }
    int j = i - XCONV_ITEMS;
    if (j < 2 * 256 * 256) {
        int op = j >> 16;
        int rem = j & 65535;
        int n = rem >> 8, k = rem & 255;
        float w;
        if (op == 0) w = (k < 128) ? Wl1[n * 128 + k] : Wr1[n * 128 + (k - 128)];
        else         w = (n < 128) ? Wl2[n * 256 + k] : Wr2[(n - 128) * 256 + k];
        __half hw = __float2half_rn(w);
        unsigned short hb = *reinterpret_cast<unsigned short*>(&hw);
        if (op == 0) g_W1[rem] = hb;
        else         g_W2[rem] = hb;
        return;
    }
    j -= 2 * 256 * 256;
    if (j < 256) g_b1[j] = bl1[j];
    else if (j < 512) {
        int n = j - 256;
        g_b2[n] = (n < 128) ? 0.0f : bl2[n - 128];
    }
}

// ---------------------------------------------------------------
// single-pass scan with decoupled lookback; also writes cur/dinv
// ---------------------------------------------------------------
__global__ void scan_kernel() {
    __shared__ int s[256];
    __shared__ int s_boff;
    int t = threadIdx.x, b = blockIdx.x;
    int i = b * 256 + t;
    int v = (i < N_NODES) ? g_degi[i] : 0;
    s[t] = v;
    __syncthreads();
#pragma unroll
    for (int off = 1; off < 256; off <<= 1) {
        int add = (t >= off) ? s[t - off] : 0;
        __syncthreads();
        s[t] += add;
        __syncthreads();
    }
    int incl = s[t];
    int agg = s[255];

    if (t == 0) {
        volatile unsigned* look = (volatile unsigned*)g_look;
        if (b == 0) {
            __threadfence();
            look[0] = (2u << 30) | (unsigned)agg;
            s_boff = 0;
        } else {
            __threadfence();
            look[b] = (1u << 30) | (unsigned)agg;
            int exc = 0;
            int j = b - 1;
            while (true) {
                unsigned pk = look[j];
                unsigned st = pk >> 30;
                if (st == 0) continue;
                exc += (int)(pk & 0x3FFFFFFFu);
                if (st == 2u) break;
                j--;
            }
            __threadfence();
            look[b] = (2u << 30) | (unsigned)(exc + agg);
            s_boff = exc;
        }
    }
    __syncthreads();
    int boff = s_boff;
    if (i < N_NODES) {
        int r = incl - v + boff;
        g_row[i] = r;
        g_cur[i] = r;
        g_dinv[i] = 1.0f / fmaxf((float)g_degi[i], 1.0f);
    }
    if (i == 0) g_row[N_NODES] = N_EDGES;
}

// group edge sources by dst (decode straight from input)
__global__ void reorder_kernel(const void* __restrict__ ei) {
    int e = blockIdx.x * blockDim.x + threadIdx.x;
    if (e >= N_EDGES) return;
    int fmt = g_fmt;
    int s = eidx_at(ei, fmt, e);
    int d = eidx_at(ei, fmt, N_EDGES + e);
    int pos = atomicAdd(&g_cur[d], 1);
    g_csrc[pos] = s;
}

// ---------------------------------------------------------------
// gather1: mean = (sum fp16 xh[neighbors]) * dinv -> A1 mean part
// ---------------------------------------------------------------
__global__ void gather1_kernel() {
    int warp = (blockIdx.x * blockDim.x + threadIdx.x) >> 5;
    int lane = threadIdx.x & 31;
    if (warp >= N_NODES) return;
    int start = g_row[warp];
    int end = g_row[warp + 1];
    float a0 = 0.f, a1 = 0.f, a2 = 0.f, a3 = 0.f;
    for (int base = start; base < end; base += 32) {
        int mye = base + lane;
        int sidx = (mye < end) ? g_csrc[mye] : 0;
        int cnt = end - base; if (cnt > 32) cnt = 32;
#pragma unroll 4
        for (int j = 0; j < cnt; j++) {
            int s = __shfl_sync(0xffffffffu, sidx, j);
            uint2 v = __ldg((const uint2*)(g_A1 + (size_t)s * 128 + 64) + lane);
            float2 f0 = __half22float2(*reinterpret_cast<__half2*>(&v.x));
            float2 f1 = __half22float2(*reinterpret_cast<__half2*>(&v.y));
            a0 += f0.x; a1 += f0.y; a2 += f1.x; a3 += f1.y;
        }
    }
    float sc = g_dinv[warp];
    __half2 p0 = __floats2half2_rn(a0 * sc, a1 * sc);
    __half2 p1 = __floats2half2_rn(a2 * sc, a3 * sc);
    size_t base = (size_t)warp * 128 + lane * 2;
    g_A1[base]     = *reinterpret_cast<unsigned*>(&p0);
    g_A1[base + 1] = *reinterpret_cast<unsigned*>(&p1);
}

// ---------------------------------------------------------------
// gather2 + final: out[n] = (sum fp16 p[nb]) * dinv[n] + q[n]
// ---------------------------------------------------------------
__global__ void gather2_kernel(float* __restrict__ out) {
    int warp = (blockIdx.x * blockDim.x + threadIdx.x) >> 5;
    int lane = threadIdx.x & 31;
    if (warp >= N_NODES) return;
    int start = g_row[warp];
    int end = g_row[warp + 1];
    float a0 = 0.f, a1 = 0.f, a2 = 0.f, a3 = 0.f;
    for (int base = start; base < end; base += 32) {
        int mye = base + lane;
        int sidx = (mye < end) ? g_csrc[mye] : 0;
        int cnt = end - base; if (cnt > 32) cnt = 32;
#pragma unroll 4
        for (int j = 0; j < cnt; j++) {
            int s = __shfl_sync(0xffffffffu, sidx, j);
            uint2 v = __ldg((const uint2*)(g_p + (size_t)s * 128) + lane);
            float2 f0 = __half22float2(*reinterpret_cast<__half2*>(&v.x));
            float2 f1 = __half22float2(*reinterpret_cast<__half2*>(&v.y));
            a0 += f0.x; a1 += f0.y; a2 += f1.x; a3 += f1.y;
        }
    }
    float s = g_dinv[warp];
    uint2 qv = __ldg((const uint2*)(g_q + (size_t)warp * 128) + lane);
    float2 q0 = __half22float2(*reinterpret_cast<__half2*>(&qv.x));
    float2 q1 = __half22float2(*reinterpret_cast<__half2*>(&qv.y));
    float4 o;
    o.x = a0 * s + q0.x;
    o.y = a1 * s + q0.y;
    o.z = a2 * s + q1.x;
    o.w = a3 * s + q1.y;
    ((float4*)(out + (size_t)warp * 128))[lane] = o;
}

// ---------------------------------------------------------------
// mma.sync fp16 GEMM, 4-stage cp.async + ldmatrix. Single term, K=256.
// mode 1 (GEMM1): ReLU -> fp16 h (A2).
// mode 0 (GEMM2): n0=0 -> fp16 p; n0=128 -> fp16 q.
// ---------------------------------------------------------------
#define SSTR 40
#define NSTG 4
#define NCH 8

__global__ void __launch_bounds__(256, 2) gemm_mma_kernel(
    const uint4* __restrict__ A4, const uint4* __restrict__ W4,
    const float* __restrict__ bias,
    __half* __restrict__ outP, __half* __restrict__ outQ,
    unsigned* __restrict__ outH,
    int M, int mode) {
    __shared__ __align__(16) unsigned short As[NSTG][128 * SSTR];
    __shared__ __align__(16) unsigned short Bs[NSTG][128 * SSTR];
    __shared__ float bsm[128];

    int tid = threadIdx.x;
    int wid = tid >> 5, lane = tid & 31;
    int wy = wid & 3, wx = wid >> 2;
    int tig = lane & 3, grp = lane >> 2;
    int m0 = blockIdx.y * 128;
    int n0 = blockIdx.x * 128;

    if (tid < 128) bsm[tid] = bias[n0 + tid];

    float acc[2][8][4];
#pragma unroll
    for (int a = 0; a < 2; a++)
#pragma unroll
        for (int b = 0; b < 8; b++)
#pragma unroll
            for (int c = 0; c < 4; c++) acc[a][b][c] = 0.f;

    int lrow = tid >> 1;
    int lc0 = (tid & 1) * 2;
    int gmA = m0 + lrow; if (gmA >= M) gmA = M - 1;
    size_t aRow = (size_t)gmA * 32;
    size_t bRow = (size_t)(n0 + lrow) * 32;

#define ISSUE(ss) do {                                                         \
        int kb_ = (ss);                                                        \
        unsigned da = su32(&As[(ss) & (NSTG - 1)][lrow * SSTR + lc0 * 8]);     \
        unsigned db = su32(&Bs[(ss) & (NSTG - 1)][lrow * SSTR + lc0 * 8]);     \
        const uint4* sa = &A4[aRow + kb_ * 4 + lc0];                           \
        const uint4* sb = &W4[bRow + kb_ * 4 + lc0];                           \
        asm volatile("cp.async.cg.shared.global [%0], [%1], 16;" :: "r"(da), "l"(sa)); \
        asm volatile("cp.async.cg.shared.global [%0], [%1], 16;" :: "r"(da + 16), "l"(sa + 1)); \
        asm volatile("cp.async.cg.shared.global [%0], [%1], 16;" :: "r"(db), "l"(sb)); \
        asm volatile("cp.async.cg.shared.global [%0], [%1], 16;" :: "r"(db + 16), "l"(sb + 1)); \
        asm volatile("cp.async.commit_group;");                                \
    } while (0)

    ISSUE(0); ISSUE(1); ISSUE(2);

    int arow = wy * 32 + (lane & 15);
    int acol = (lane >> 4);
    int brow = wx * 64 + ((lane >> 4) & 1) * 8 + (lane & 7);
    int bcol = (lane >> 3) & 1;

    for (int c = 0; c < NCH; c++) {
        if (c <= NCH - 3)      asm volatile("cp.async.wait_group 2;");
        else if (c == NCH - 2) asm volatile("cp.async.wait_group 1;");
        else                   asm volatile("cp.async.wait_group 0;");
        __syncthreads();
        if (c + 3 < NCH) ISSUE(c + 3);

        int b = c & (NSTG - 1);
        const unsigned short* As_ = As[b];
        const unsigned short* Bs_ = Bs[b];
#pragma unroll
        for (int ks = 0; ks < 2; ks++) {
            unsigned af[2][4];
#pragma unroll
            for (int mt = 0; mt < 2; mt++) {
                unsigned addr = su32(&As_[(arow + mt * 16) * SSTR + (ks * 2 + acol) * 8]);
                asm volatile(
                    "ldmatrix.sync.aligned.m8n8.x4.shared.b16 {%0,%1,%2,%3}, [%4];"
                    : "=r"(af[mt][0]), "=r"(af[mt][1]), "=r"(af[mt][2]), "=r"(af[mt][3])
                    : "r"(addr));
            }
#pragma unroll
            for (int g = 0; g < 4; g++) {
                unsigned bf[4];
                unsigned addr = su32(&Bs_[(brow + g * 16) * SSTR + (ks * 2 + bcol) * 8]);
                asm volatile(
                    "ldmatrix.sync.aligned.m8n8.x4.shared.b16 {%0,%1,%2,%3}, [%4];"
                    : "=r"(bf[0]), "=r"(bf[1]), "=r"(bf[2]), "=r"(bf[3])
                    : "r"(addr));
#pragma unroll
                for (int mt = 0; mt < 2; mt++) {
                    asm volatile(
                        "mma.sync.aligned.m16n8k16.row.col.f32.f16.f16.f32 "
                        "{%0,%1,%2,%3}, {%4,%5,%6,%7}, {%8,%9}, {%0,%1,%2,%3};"
                        : "+f"(acc[mt][2 * g][0]), "+f"(acc[mt][2 * g][1]),
                          "+f"(acc[mt][2 * g][2]), "+f"(acc[mt][2 * g][3])
                        : "r"(af[mt][0]), "r"(af[mt][1]),
                          "r"(af[mt][2]), "r"(af[mt][3]),
                          "r"(bf[0]), "r"(bf[1]));
                    asm volatile(
                        "mma.sync.aligned.m16n8k16.row.col.f32.f16.f16.f32 "
                        "{%0,%1,%2,%3}, {%4,%5,%6,%7}, {%8,%9}, {%0,%1,%2,%3};"
                        : "+f"(acc[mt][2 * g + 1][0]), "+f"(acc[mt][2 * g + 1][1]),
                          "+f"(acc[mt][2 * g + 1][2]), "+f"(acc[mt][2 * g + 1][3])
                        : "r"(af[mt][0]), "r"(af[mt][1]),
                          "r"(af[mt][2]), "r"(af[mt][3]),
                          "r"(bf[2]), "r"(bf[3]));
                }
            }
        }
    }

    // epilogue
#pragma unroll
    for (int mt = 0; mt < 2; mt++) {
        int gm0 = m0 + wy * 32 + mt * 16 + grp;
#pragma unroll
        for (int nt = 0; nt < 8; nt++) {
            int nl = wx * 64 + nt * 8 + tig * 2;
            float bx = bsm[nl], by = bsm[nl + 1];
            float v0 = acc[mt][nt][0] + bx;
            float v1 = acc[mt][nt][1] + by;
            float v2 = acc[mt][nt][2] + bx;
            float v3 = acc[mt][nt][3] + by;
            if (mode == 1) {
                v0 = fmaxf(v0, 0.f); v1 = fmaxf(v1, 0.f);
                v2 = fmaxf(v2, 0.f); v3 = fmaxf(v3, 0.f);
                __half2 h01 = __floats2half2_rn(v0, v1);
                __half2 h23 = __floats2half2_rn(v2, v3);
                if (gm0 < M)
                    outH[(size_t)gm0 * 128 + (nl >> 1) + n0 / 2] =
                        *reinterpret_cast<unsigned*>(&h01);
                if (gm0 + 8 < M)
                    outH[(size_t)(gm0 + 8) * 128 + (nl >> 1) + n0 / 2] =
                        *reinterpret_cast<unsigned*>(&h23);
            } else {
                __half* dst = (n0 == 0) ? outP : outQ;
                if (gm0 < M)
                    *(__half2*)(dst + (size_t)gm0 * 128 + nl) = __floats2half2_rn(v0, v1);
                if (gm0 + 8 < M)
                    *(__half2*)(dst + (size_t)(gm0 + 8) * 128 + nl) = __floats2half2_rn(v2, v3);
            }
        }
    }
#undef ISSUE
}

// ---------------------------------------------------------------
// launch — inputs: x, Wl1, bl1, Wr1, Wl2, bl2, Wr2, edge_index
// ---------------------------------------------------------------
extern "C" void kernel_launch(void* const* d_in, const int* in_sizes, int n_in,
                              void* d_out, int out_size) {
    const float* x   = (const float*)d_in[0];
    const float* Wl1 = (const float*)d_in[1];
    const float* bl1 = (const float*)d_in[2];
    const float* Wr1 = (const float*)d_in[3];
    const float* Wl2 = (const float*)d_in[4];
    const float* bl2 = (const float*)d_in[5];
    const float* Wr2 = (const float*)d_in[6];
    const void*  ei  = d_in[7];
    float* out = (float*)d_out;

    unsigned *A1, *A2;
    unsigned short *W1, *W2;
    float *b1, *b2;
    __half *p, *q;
    cudaGetSymbolAddress((void**)&A1, g_A1);
    cudaGetSymbolAddress((void**)&A2, g_A2);
    cudaGetSymbolAddress((void**)&W1, g_W1);
    cudaGetSymbolAddress((void**)&W2, g_W2);
    cudaGetSymbolAddress((void**)&b1, g_b1);
    cudaGetSymbolAddress((void**)&b2, g_b2);
    cudaGetSymbolAddress((void**)&p, g_p);
    cudaGetSymbolAddress((void**)&q, g_q);

    // 0. init (degree zero + lookback reset + format probe)
    init_kernel<<<(N_NODES + 255) / 256, 256>>>((const int*)ei);

    // 1. fused degree count + prep (x fp16 + weights/biases)
    degprep_kernel<<<DEG_NB + PREP_NB, 256>>>(ei, x, Wl1, Wr1, Wl2, Wr2, bl1, bl2);

    // 2. single-pass lookback scan (row/cur/dinv)
    scan_kernel<<<SCAN_NB, 256>>>();

    // 3. reorder (decodes from input directly)
    reorder_kernel<<<(N_EDGES + 255) / 256, 256>>>(ei);

    // 4. layer-1 gather (fp16 x) -> A1 mean part
    gather1_kernel<<<(N_NODES + 7) / 8, 256>>>();

    // 5. GEMM1: h = relu([mean|x]@[Wl1|Wr1]ᵀ + b1) -> A2 fp16
    {
        dim3 grid(2, GEMM_MB);
        gemm_mma_kernel<<<grid, 256>>>((const uint4*)A1, (const uint4*)W1, b1,
                                       nullptr, nullptr, A2, N_NODES, 1);
    }

    // 6. GEMM2: p = h@Wl2ᵀ (fp16), q = h@Wr2ᵀ + bl2 (fp16)
    {
        dim3 grid(2, GEMM_MB);
        gemm_mma_kernel<<<grid, 256>>>((const uint4*)A2, (const uint4*)W2, b2,
                                       p, q, nullptr, N_NODES, 0);
    }

    // 7. layer-2 gather on fp16 p, fused with final combine
    gather2_kernel<<<(N_NODES + 7) / 8, 256>>>(out);
}

// round 15
// speedup vs baseline: 1.0613x; 1.0613x over previous
#include <cuda_runtime.h>
#include <cuda_fp16.h>
#include <cstdint>
#include <cstddef>

#define N_NODES 50000
#define N_EDGES 800000
#define SCAN_NB ((N_NODES + 255) / 256)   // 196 blocks
#define GEMM_MB ((N_NODES + 127) / 128)   // 391 CTAs in M
#define XCONV_ITEMS (N_NODES * 32)

// ---- device scratch ----
// A1: fp16 [M,256] packed as uints (row stride 128 uints)
// layout: uints 0..63 = mean part (128 fp16), uints 64..127 = x part
__device__ __align__(16) unsigned g_A1[(size_t)N_NODES * 128];
__device__ __align__(16) unsigned g_A2[(size_t)N_NODES * 128];   // h fp16
__device__ __align__(16) __half   g_p[(size_t)N_NODES * 128];    // p fp16
__device__ __align__(16) __half   g_q[(size_t)N_NODES * 128];    // q fp16
__device__ __align__(16) unsigned short g_W1[256 * 256];         // fp16
__device__ __align__(16) unsigned short g_W2[256 * 256];         // fp16
__device__ __align__(16) float g_b1[256];
__device__ __align__(16) float g_b2[256];
__device__ __align__(16) float g_dinv[N_NODES];
__device__ __align__(16) int   g_degi[N_NODES];
__device__ __align__(16) int   g_row[N_NODES + 1];
__device__ __align__(16) int   g_cur[N_NODES];
__device__ __align__(16) int   g_csrc[N_EDGES];
__device__ __align__(16) int   g_bsum[SCAN_NB];
__device__ int g_fmt;

// ---------------- helpers ----------------
__device__ __forceinline__ unsigned su32(const void* p) {
    return (unsigned)__cvta_generic_to_shared(p);
}

__device__ __forceinline__ int eidx_at(const void* ei, int fmt, int i) {
    return fmt ? (int)((const long long*)ei)[i] : ((const int*)ei)[i];
}

// ---------------------------------------------------------------
// init: zero degrees + parallel edge-format probe (block 0)
// ---------------------------------------------------------------
__global__ void init_kernel(const int* __restrict__ ei32) {
    int i = blockIdx.x * blockDim.x + threadIdx.x;
    if (i < N_NODES) g_degi[i] = 0;
    if (blockIdx.x == 0) {
        __shared__ int s_nz;
        if (threadIdx.x == 0) s_nz = 0;
        __syncthreads();
        int nz = 0;
        for (int k = threadIdx.x; k < 512; k += 256)
            nz |= (ei32[2 * k + 1] != 0);
        if (nz) atomicOr(&s_nz, 1);
        __syncthreads();
        if (threadIdx.x == 0) g_fmt = s_nz ? 0 : 1;
    }
}

// degree count: decode dst half of edge_index directly
__global__ void deg_kernel(const void* __restrict__ ei) {
    int e = blockIdx.x * blockDim.x + threadIdx.x;
    if (e >= N_EDGES) return;
    int d = eidx_at(ei, g_fmt, N_EDGES + e);
    atomicAdd(&g_degi[d], 1);
}

__global__ void scan_blocks_kernel() {
    __shared__ int s[256];
    int t = threadIdx.x;
    int i = blockIdx.x * 256 + t;
    int v = (i < N_NODES) ? g_degi[i] : 0;
    s[t] = v;
    __syncthreads();
#pragma unroll
    for (int off = 1; off < 256; off <<= 1) {
        int add = (t >= off) ? s[t - off] : 0;
        __syncthreads();
        s[t] += add;
        __syncthreads();
    }
    int incl = s[t];
    if (i < N_NODES) g_row[i] = incl - v;
    if (t == 255) g_bsum[blockIdx.x] = incl;
}

__global__ void scan_finish_kernel() {
    __shared__ int red[256];
    int t = threadIdx.x;
    int partial = 0;
    for (int k = t; k < blockIdx.x; k += 256) partial += g_bsum[k];
    red[t] = partial;
    __syncthreads();
#pragma unroll
    for (int s = 128; s > 0; s >>= 1) {
        if (t < s) red[t] += red[t + s];
        __syncthreads();
    }
    int boff = red[0];
    int i = blockIdx.x * 256 + t;
    if (i < N_NODES) {
        int r = g_row[i] + boff;
        g_row[i] = r;
        g_cur[i] = r;
        g_dinv[i] = 1.0f / fmaxf((float)g_degi[i], 1.0f);
    }
    if (i == 0) g_row[N_NODES] = N_EDGES;
}

// group edge sources by dst (decode straight from input)
__global__ void reorder_kernel(const void* __restrict__ ei) {
    int e = blockIdx.x * blockDim.x + threadIdx.x;
    if (e >= N_EDGES) return;
    int fmt = g_fmt;
    int s = eidx_at(ei, fmt, e);
    int d = eidx_at(ei, fmt, N_EDGES + e);
    int pos = atomicAdd(&g_cur[d], 1);
    g_csrc[pos] = s;
}

// ---------------------------------------------------------------
// prep: fused x fp16 conversion + weight/bias conversion
// ---------------------------------------------------------------
__global__ void prep_kernel(const float* __restrict__ x,
                            const float* __restrict__ Wl1, const float* __restrict__ Wr1,
                            const float* __restrict__ Wl2, const float* __restrict__ Wr2,
                            const float* __restrict__ bl1, const float* __restrict__ bl2) {
    int i = blockIdx.x * blockDim.x + threadIdx.x;
    if (i < XCONV_ITEMS) {
        int m = i >> 5, c4 = i & 31;
        float4 v = ((const float4*)x)[i];
        __half2 p0 = __floats2half2_rn(v.x, v.y);
        __half2 p1 = __floats2half2_rn(v.z, v.w);
        size_t base = (size_t)m * 128 + 64 + c4 * 2;
        g_A1[base]     = *reinterpret_cast<unsigned*>(&p0);
        g_A1[base + 1] = *reinterpret_cast<unsigned*>(&p1);
        return;
    }
    int j = i - XCONV_ITEMS;
    if (j < 2 * 256 * 256) {
        int op = j >> 16;
        int rem = j & 65535;
        int n = rem >> 8, k = rem & 255;
        float w;
        if (op == 0) w = (k < 128) ? Wl1[n * 128 + k] : Wr1[n * 128 + (k - 128)];
        else         w = (n < 128) ? Wl2[n * 256 + k] : Wr2[(n - 128) * 256 + k];
        __half hw = __float2half_rn(w);
        unsigned short hb = *reinterpret_cast<unsigned short*>(&hw);
        if (op == 0) g_W1[rem] = hb;
        else         g_W2[rem] = hb;
        return;
    }
    j -= 2 * 256 * 256;
    if (j < 256) g_b1[j] = bl1[j];
    else if (j < 512) {
        int n = j - 256;
        g_b2[n] = (n < 128) ? 0.0f : bl2[n - 128];
    }
}

// ---------------------------------------------------------------
// gather1: mean = (sum fp16 xh[neighbors]) * dinv -> A1 mean part
// ---------------------------------------------------------------
__global__ void gather1_kernel() {
    int warp = (blockIdx.x * blockDim.x + threadIdx.x) >> 5;
    int lane = threadIdx.x & 31;
    if (warp >= N_NODES) return;
    int start = g_row[warp];
    int end = g_row[warp + 1];
    float a0 = 0.f, a1 = 0.f, a2 = 0.f, a3 = 0.f;
    for (int base = start; base < end; base += 32) {
        int mye = base + lane;
        int sidx = (mye < end) ? g_csrc[mye] : 0;
        int cnt = end - base; if (cnt > 32) cnt = 32;
#pragma unroll 4
        for (int j = 0; j < cnt; j++) {
            int s = __shfl_sync(0xffffffffu, sidx, j);
            uint2 v = __ldg((const uint2*)(g_A1 + (size_t)s * 128 + 64) + lane);
            float2 f0 = __half22float2(*reinterpret_cast<__half2*>(&v.x));
            float2 f1 = __half22float2(*reinterpret_cast<__half2*>(&v.y));
            a0 += f0.x; a1 += f0.y; a2 += f1.x; a3 += f1.y;
        }
    }
    float sc = g_dinv[warp];
    __half2 p0 = __floats2half2_rn(a0 * sc, a1 * sc);
    __half2 p1 = __floats2half2_rn(a2 * sc, a3 * sc);
    size_t base = (size_t)warp * 128 + lane * 2;
    g_A1[base]     = *reinterpret_cast<unsigned*>(&p0);
    g_A1[base + 1] = *reinterpret_cast<unsigned*>(&p1);
}

// ---------------------------------------------------------------
// gather2 + final: out[n] = (sum fp16 p[nb]) * dinv[n] + q[n]
// ---------------------------------------------------------------
__global__ void gather2_kernel(float* __restrict__ out) {
    int warp = (blockIdx.x * blockDim.x + threadIdx.x) >> 5;
    int lane = threadIdx.x & 31;
    if (warp >= N_NODES) return;
    int start = g_row[warp];
    int end = g_row[warp + 1];
    float a0 = 0.f, a1 = 0.f, a2 = 0.f, a3 = 0.f;
    for (int base = start; base < end; base += 32) {
        int mye = base + lane;
        int sidx = (mye < end) ? g_csrc[mye] : 0;
        int cnt = end - base; if (cnt > 32) cnt = 32;
#pragma unroll 4
        for (int j = 0; j < cnt; j++) {
            int s = __shfl_sync(0xffffffffu, sidx, j);
            uint2 v = __ldg((const uint2*)(g_p + (size_t)s * 128) + lane);
            float2 f0 = __half22float2(*reinterpret_cast<__half2*>(&v.x));
            float2 f1 = __half22float2(*reinterpret_cast<__half2*>(&v.y));
            a0 += f0.x; a1 += f0.y; a2 += f1.x; a3 += f1.y;
        }
    }
    float s = g_dinv[warp];
    uint2 qv = __ldg((const uint2*)(g_q + (size_t)warp * 128) + lane);
    float2 q0 = __half22float2(*reinterpret_cast<__half2*>(&qv.x));
    float2 q1 = __half22float2(*reinterpret_cast<__half2*>(&qv.y));
    float4 o;
    o.x = a0 * s + q0.x;
    o.y = a1 * s + q0.y;
    o.z = a2 * s + q1.x;
    o.w = a3 * s + q1.y;
    ((float4*)(out + (size_t)warp * 128))[lane] = o;
}

// ---------------------------------------------------------------
// mma.sync fp16 GEMM, 4-stage cp.async + ldmatrix. Single term, K=256.
// mode 1 (GEMM1): ReLU -> fp16 h (A2).
// mode 0 (GEMM2): n0=0 -> fp16 p; n0=128 -> fp16 q.
// ---------------------------------------------------------------
#define SSTR 40
#define NSTG 4
#define NCH 8

__global__ void __launch_bounds__(256, 2) gemm_mma_kernel(
    const uint4* __restrict__ A4, const uint4* __restrict__ W4,
    const float* __restrict__ bias,
    __half* __restrict__ outP, __half* __restrict__ outQ,
    unsigned* __restrict__ outH,
    int M, int mode) {
    __shared__ __align__(16) unsigned short As[NSTG][128 * SSTR];
    __shared__ __align__(16) unsigned short Bs[NSTG][128 * SSTR];
    __shared__ float bsm[128];

    int tid = threadIdx.x;
    int wid = tid >> 5, lane = tid & 31;
    int wy = wid & 3, wx = wid >> 2;
    int tig = lane & 3, grp = lane >> 2;
    int m0 = blockIdx.y * 128;
    int n0 = blockIdx.x * 128;

    if (tid < 128) bsm[tid] = bias[n0 + tid];

    float acc[2][8][4];
#pragma unroll
    for (int a = 0; a < 2; a++)
#pragma unroll
        for (int b = 0; b < 8; b++)
#pragma unroll
            for (int c = 0; c < 4; c++) acc[a][b][c] = 0.f;

    int lrow = tid >> 1;
    int lc0 = (tid & 1) * 2;
    int gmA = m0 + lrow; if (gmA >= M) gmA = M - 1;
    size_t aRow = (size_t)gmA * 32;
    size_t bRow = (size_t)(n0 + lrow) * 32;

#define ISSUE(ss) do {                                                         \
        int kb_ = (ss);                                                        \
        unsigned da = su32(&As[(ss) & (NSTG - 1)][lrow * SSTR + lc0 * 8]);     \
        unsigned db = su32(&Bs[(ss) & (NSTG - 1)][lrow * SSTR + lc0 * 8]);     \
        const uint4* sa = &A4[aRow + kb_ * 4 + lc0];                           \
        const uint4* sb = &W4[bRow + kb_ * 4 + lc0];                           \
        asm volatile("cp.async.cg.shared.global [%0], [%1], 16;" :: "r"(da), "l"(sa)); \
        asm volatile("cp.async.cg.shared.global [%0], [%1], 16;" :: "r"(da + 16), "l"(sa + 1)); \
        asm volatile("cp.async.cg.shared.global [%0], [%1], 16;" :: "r"(db), "l"(sb)); \
        asm volatile("cp.async.cg.shared.global [%0], [%1], 16;" :: "r"(db + 16), "l"(sb + 1)); \
        asm volatile("cp.async.commit_group;");                                \
    } while (0)

    ISSUE(0); ISSUE(1); ISSUE(2);

    int arow = wy * 32 + (lane & 15);
    int acol = (lane >> 4);
    int brow = wx * 64 + ((lane >> 4) & 1) * 8 + (lane & 7);
    int bcol = (lane >> 3) & 1;

    for (int c = 0; c < NCH; c++) {
        if (c <= NCH - 3)      asm volatile("cp.async.wait_group 2;");
        else if (c == NCH - 2) asm volatile("cp.async.wait_group 1;");
        else                   asm volatile("cp.async.wait_group 0;");
        __syncthreads();
        if (c + 3 < NCH) ISSUE(c + 3);

        int b = c & (NSTG - 1);
        const unsigned short* As_ = As[b];
        const unsigned short* Bs_ = Bs[b];
#pragma unroll
        for (int ks = 0; ks < 2; ks++) {
            unsigned af[2][4];
#pragma unroll
            for (int mt = 0; mt < 2; mt++) {
                unsigned addr = su32(&As_[(arow + mt * 16) * SSTR + (ks * 2 + acol) * 8]);
                asm volatile(
                    "ldmatrix.sync.aligned.m8n8.x4.shared.b16 {%0,%1,%2,%3}, [%4];"
                    : "=r"(af[mt][0]), "=r"(af[mt][1]), "=r"(af[mt][2]), "=r"(af[mt][3])
                    : "r"(addr));
            }
#pragma unroll
            for (int g = 0; g < 4; g++) {
                unsigned bf[4];
                unsigned addr = su32(&Bs_[(brow + g * 16) * SSTR + (ks * 2 + bcol) * 8]);
                asm volatile(
                    "ldmatrix.sync.aligned.m8n8.x4.shared.b16 {%0,%1,%2,%3}, [%4];"
                    : "=r"(bf[0]), "=r"(bf[1]), "=r"(bf[2]), "=r"(bf[3])
                    : "r"(addr));
#pragma unroll
                for (int mt = 0; mt < 2; mt++) {
                    asm volatile(
                        "mma.sync.aligned.m16n8k16.row.col.f32.f16.f16.f32 "
                        "{%0,%1,%2,%3}, {%4,%5,%6,%7}, {%8,%9}, {%0,%1,%2,%3};"
                        : "+f"(acc[mt][2 * g][0]), "+f"(acc[mt][2 * g][1]),
                          "+f"(acc[mt][2 * g][2]), "+f"(acc[mt][2 * g][3])
                        : "r"(af[mt][0]), "r"(af[mt][1]),
                          "r"(af[mt][2]), "r"(af[mt][3]),
                          "r"(bf[0]), "r"(bf[1]));
                    asm volatile(
                        "mma.sync.aligned.m16n8k16.row.col.f32.f16.f16.f32 "
                        "{%0,%1,%2,%3}, {%4,%5,%6,%7}, {%8,%9}, {%0,%1,%2,%3};"
                        : "+f"(acc[mt][2 * g + 1][0]), "+f"(acc[mt][2 * g + 1][1]),
                          "+f"(acc[mt][2 * g + 1][2]), "+f"(acc[mt][2 * g + 1][3])
                        : "r"(af[mt][0]), "r"(af[mt][1]),
                          "r"(af[mt][2]), "r"(af[mt][3]),
                          "r"(bf[2]), "r"(bf[3]));
                }
            }
        }
    }

    // epilogue
#pragma unroll
    for (int mt = 0; mt < 2; mt++) {
        int gm0 = m0 + wy * 32 + mt * 16 + grp;
#pragma unroll
        for (int nt = 0; nt < 8; nt++) {
            int nl = wx * 64 + nt * 8 + tig * 2;
            float bx = bsm[nl], by = bsm[nl + 1];
            float v0 = acc[mt][nt][0] + bx;
            float v1 = acc[mt][nt][1] + by;
            float v2 = acc[mt][nt][2] + bx;
            float v3 = acc[mt][nt][3] + by;
            if (mode == 1) {
                v0 = fmaxf(v0, 0.f); v1 = fmaxf(v1, 0.f);
                v2 = fmaxf(v2, 0.f); v3 = fmaxf(v3, 0.f);
                __half2 h01 = __floats2half2_rn(v0, v1);
                __half2 h23 = __floats2half2_rn(v2, v3);
                if (gm0 < M)
                    outH[(size_t)gm0 * 128 + (nl >> 1) + n0 / 2] =
                        *reinterpret_cast<unsigned*>(&h01);
                if (gm0 + 8 < M)
                    outH[(size_t)(gm0 + 8) * 128 + (nl >> 1) + n0 / 2] =
                        *reinterpret_cast<unsigned*>(&h23);
            } else {
                __half* dst = (n0 == 0) ? outP : outQ;
                if (gm0 < M)
                    *(__half2*)(dst + (size_t)gm0 * 128 + nl) = __floats2half2_rn(v0, v1);
                if (gm0 + 8 < M)
                    *(__half2*)(dst + (size_t)(gm0 + 8) * 128 + nl) = __floats2half2_rn(v2, v3);
            }
        }
    }
#undef ISSUE
}

// ---------------------------------------------------------------
// launch — inputs: x, Wl1, bl1, Wr1, Wl2, bl2, Wr2, edge_index
// ---------------------------------------------------------------
extern "C" void kernel_launch(void* const* d_in, const int* in_sizes, int n_in,
                              void* d_out, int out_size) {
    const float* x   = (const float*)d_in[0];
    const float* Wl1 = (const float*)d_in[1];
    const float* bl1 = (const float*)d_in[2];
    const float* Wr1 = (const float*)d_in[3];
    const float* Wl2 = (const float*)d_in[4];
    const float* bl2 = (const float*)d_in[5];
    const float* Wr2 = (const float*)d_in[6];
    const void*  ei  = d_in[7];
    float* out = (float*)d_out;

    unsigned *A1, *A2;
    unsigned short *W1, *W2;
    float *b1, *b2;
    __half *p, *q;
    cudaGetSymbolAddress((void**)&A1, g_A1);
    cudaGetSymbolAddress((void**)&A2, g_A2);
    cudaGetSymbolAddress((void**)&W1, g_W1);
    cudaGetSymbolAddress((void**)&W2, g_W2);
    cudaGetSymbolAddress((void**)&b1, g_b1);
    cudaGetSymbolAddress((void**)&b2, g_b2);
    cudaGetSymbolAddress((void**)&p, g_p);
    cudaGetSymbolAddress((void**)&q, g_q);

    // 0. init (degree zero + format probe), then degree count
    init_kernel<<<(N_NODES + 255) / 256, 256>>>((const int*)ei);
    deg_kernel<<<(N_EDGES + 255) / 256, 256>>>(ei);

    // 1. CSR build (2-pass scan) + reorder (decodes from input directly)
    scan_blocks_kernel<<<SCAN_NB, 256>>>();
    scan_finish_kernel<<<SCAN_NB, 256>>>();
    reorder_kernel<<<(N_EDGES + 255) / 256, 256>>>(ei);

    // 2. fused prep: x fp16 + weights/biases
    {
        int items = XCONV_ITEMS + 2 * 256 * 256 + 512;
        prep_kernel<<<(items + 255) / 256, 256>>>(x, Wl1, Wr1, Wl2, Wr2, bl1, bl2);
    }

    // 3. layer-1 gather (fp16 x) -> A1 mean part
    gather1_kernel<<<(N_NODES + 7) / 8, 256>>>();

    // 4. GEMM1: h = relu([mean|x]@[Wl1|Wr1]ᵀ + b1) -> A2 fp16
    {
        dim3 grid(2, GEMM_MB);
        gemm_mma_kernel<<<grid, 256>>>((const uint4*)A1, (const uint4*)W1, b1,
                                       nullptr, nullptr, A2, N_NODES, 1);
    }

    // 5. GEMM2: p = h@Wl2ᵀ (fp16), q = h@Wr2ᵀ + bl2 (fp16)
    {
        dim3 grid(2, GEMM_MB);
        gemm_mma_kernel<<<grid, 256>>>((const uint4*)A2, (const uint4*)W2, b2,
                                       p, q, nullptr, N_NODES, 0);
    }

    // 6. layer-2 gather on fp16 p, fused with final combine
    gather2_kernel<<<(N_NODES + 7) / 8, 256>>>(out);
}

// round 16
// speedup vs baseline: 1.0631x; 1.0017x over previous
#include <cuda_runtime.h>
#include <cuda_fp16.h>
#include <cstdint>
#include <cstddef>

#define N_NODES 50000
#define N_EDGES 800000
#define SCAN_NB ((N_NODES + 255) / 256)   // 196 blocks
#define GEMM_MB ((N_NODES + 127) / 128)   // 391 CTAs in M
#define XCONV_ITEMS (N_NODES * 32)
#define EPT 4                              // edges per thread in edge passes
#define EDGE_NB ((N_EDGES / EPT + 255) / 256)

// ---- device scratch ----
// A1: fp16 [M,256] packed as uints (row stride 128 uints)
// layout: uints 0..63 = mean part (128 fp16), uints 64..127 = x part
__device__ __align__(16) unsigned g_A1[(size_t)N_NODES * 128];
__device__ __align__(16) unsigned g_A2[(size_t)N_NODES * 128];   // h fp16
__device__ __align__(16) __half   g_p[(size_t)N_NODES * 128];    // p fp16
__device__ __align__(16) __half   g_q[(size_t)N_NODES * 128];    // q fp16
__device__ __align__(16) unsigned short g_W1[256 * 256];         // fp16
__device__ __align__(16) unsigned short g_W2[256 * 256];         // fp16
__device__ __align__(16) float g_b1[256];
__device__ __align__(16) float g_b2[256];
__device__ __align__(16) float g_dinv[N_NODES];
__device__ __align__(16) int   g_degi[N_NODES];
__device__ __align__(16) int   g_row[N_NODES + 1];
__device__ __align__(16) int   g_cur[N_NODES];
__device__ __align__(16) int   g_csrc[N_EDGES];
__device__ __align__(16) int   g_bsum[SCAN_NB];
__device__ int g_fmt;

// ---------------- helpers ----------------
__device__ __forceinline__ unsigned su32(const void* p) {
    return (unsigned)__cvta_generic_to_shared(p);
}

// decode 4 consecutive edge entries starting at index i (i % 4 == 0)
__device__ __forceinline__ void eidx4(const void* ei, int fmt, int i, int* v) {
    if (fmt) {
        const longlong2* p = (const longlong2*)((const long long*)ei + i);
        longlong2 a = __ldg(p);
        longlong2 b = __ldg(p + 1);
        v[0] = (int)a.x; v[1] = (int)a.y; v[2] = (int)b.x; v[3] = (int)b.y;
    } else {
        int4 a = __ldg((const int4*)((const int*)ei + i));
        v[0] = a.x; v[1] = a.y; v[2] = a.z; v[3] = a.w;
    }
}

// ---------------------------------------------------------------
// init: zero degrees + parallel edge-format probe (block 0)
// ---------------------------------------------------------------
__global__ void init_kernel(const int* __restrict__ ei32) {
    int i = blockIdx.x * blockDim.x + threadIdx.x;
    if (i < N_NODES) g_degi[i] = 0;
    if (blockIdx.x == 0) {
        __shared__ int s_nz;
        if (threadIdx.x == 0) s_nz = 0;
        __syncthreads();
        int nz = 0;
        for (int k = threadIdx.x; k < 512; k += 256)
            nz |= (ei32[2 * k + 1] != 0);
        if (nz) atomicOr(&s_nz, 1);
        __syncthreads();
        if (threadIdx.x == 0) g_fmt = s_nz ? 0 : 1;
    }
}

// degree count: 4 edges per thread, vectorized decode of dst half
__global__ void deg_kernel(const void* __restrict__ ei) {
    int base = (blockIdx.x * blockDim.x + threadIdx.x) * EPT;
    if (base >= N_EDGES) return;
    int d[EPT];
    eidx4(ei, g_fmt, N_EDGES + base, d);
#pragma unroll
    for (int k = 0; k < EPT; k++) atomicAdd(&g_degi[d[k]], 1);
}

__global__ void scan_blocks_kernel() {
    __shared__ int s[256];
    int t = threadIdx.x;
    int i = blockIdx.x * 256 + t;
    int v = (i < N_NODES) ? g_degi[i] : 0;
    s[t] = v;
    __syncthreads();
#pragma unroll
    for (int off = 1; off < 256; off <<= 1) {
        int add = (t >= off) ? s[t - off] : 0;
        __syncthreads();
        s[t] += add;
        __syncthreads();
    }
    int incl = s[t];
    if (i < N_NODES) g_row[i] = incl - v;
    if (t == 255) g_bsum[blockIdx.x] = incl;
}

__global__ void scan_finish_kernel() {
    __shared__ int red[256];
    int t = threadIdx.x;
    int partial = 0;
    for (int k = t; k < blockIdx.x; k += 256) partial += g_bsum[k];
    red[t] = partial;
    __syncthreads();
#pragma unroll
    for (int s = 128; s > 0; s >>= 1) {
        if (t < s) red[t] += red[t + s];
        __syncthreads();
    }
    int boff = red[0];
    int i = blockIdx.x * 256 + t;
    if (i < N_NODES) {
        int r = g_row[i] + boff;
        g_row[i] = r;
        g_cur[i] = r;
        g_dinv[i] = 1.0f / fmaxf((float)g_degi[i], 1.0f);
    }
    if (i == 0) g_row[N_NODES] = N_EDGES;
}

// group edge sources by dst: 4 edges per thread, vectorized decode
__global__ void reorder_kernel(const void* __restrict__ ei) {
    int base = (blockIdx.x * blockDim.x + threadIdx.x) * EPT;
    if (base >= N_EDGES) return;
    int fmt = g_fmt;
    int s[EPT], d[EPT];
    eidx4(ei, fmt, base, s);
    eidx4(ei, fmt, N_EDGES + base, d);
#pragma unroll
    for (int k = 0; k < EPT; k++) {
        int pos = atomicAdd(&g_cur[d[k]], 1);
        g_csrc[pos] = s[k];
    }
}

// ---------------------------------------------------------------
// prep: fused x fp16 conversion + weight/bias conversion
// ---------------------------------------------------------------
__global__ void prep_kernel(const float* __restrict__ x,
                            const float* __restrict__ Wl1, const float* __restrict__ Wr1,
                            const float* __restrict__ Wl2, const float* __restrict__ Wr2,
                            const float* __restrict__ bl1, const float* __restrict__ bl2) {
    int i = blockIdx.x * blockDim.x + threadIdx.x;
    if (i < XCONV_ITEMS) {
        int m = i >> 5, c4 = i & 31;
        float4 v = ((const float4*)x)[i];
        __half2 p0 = __floats2half2_rn(v.x, v.y);
        __half2 p1 = __floats2half2_rn(v.z, v.w);
        size_t base = (size_t)m * 128 + 64 + c4 * 2;
        g_A1[base]     = *reinterpret_cast<unsigned*>(&p0);
        g_A1[base + 1] = *reinterpret_cast<unsigned*>(&p1);
        return;
    }
    int j = i - XCONV_ITEMS;
    if (j < 2 * 256 * 256) {
        int op = j >> 16;
        int rem = j & 65535;
        int n = rem >> 8, k = rem & 255;
        float w;
        if (op == 0) w = (k < 128) ? Wl1[n * 128 + k] : Wr1[n * 128 + (k - 128)];
        else         w = (n < 128) ? Wl2[n * 256 + k] : Wr2[(n - 128) * 256 + k];
        __half hw = __float2half_rn(w);
        unsigned short hb = *reinterpret_cast<unsigned short*>(&hw);
        if (op == 0) g_W1[rem] = hb;
        else         g_W2[rem] = hb;
        return;
    }
    j -= 2 * 256 * 256;
    if (j < 256) g_b1[j] = bl1[j];
    else if (j < 512) {
        int n = j - 256;
        g_b2[n] = (n < 128) ? 0.0f : bl2[n - 128];
    }
}

// ---------------------------------------------------------------
// gather1: mean = (sum fp16 xh[neighbors]) * dinv -> A1 mean part
// ---------------------------------------------------------------
__global__ void gather1_kernel() {
    int warp = (blockIdx.x * blockDim.x + threadIdx.x) >> 5;
    int lane = threadIdx.x & 31;
    if (warp >= N_NODES) return;
    int start = g_row[warp];
    int end = g_row[warp + 1];
    float a0 = 0.f, a1 = 0.f, a2 = 0.f, a3 = 0.f;
    for (int base = start; base < end; base += 32) {
        int mye = base + lane;
        int sidx = (mye < end) ? g_csrc[mye] : 0;
        int cnt = end - base; if (cnt > 32) cnt = 32;
#pragma unroll 4
        for (int j = 0; j < cnt; j++) {
            int s = __shfl_sync(0xffffffffu, sidx, j);
            uint2 v = __ldg((const uint2*)(g_A1 + (size_t)s * 128 + 64) + lane);
            float2 f0 = __half22float2(*reinterpret_cast<__half2*>(&v.x));
            float2 f1 = __half22float2(*reinterpret_cast<__half2*>(&v.y));
            a0 += f0.x; a1 += f0.y; a2 += f1.x; a3 += f1.y;
        }
    }
    float sc = g_dinv[warp];
    __half2 p0 = __floats2half2_rn(a0 * sc, a1 * sc);
    __half2 p1 = __floats2half2_rn(a2 * sc, a3 * sc);
    size_t base = (size_t)warp * 128 + lane * 2;
    g_A1[base]     = *reinterpret_cast<unsigned*>(&p0);
    g_A1[base + 1] = *reinterpret_cast<unsigned*>(&p1);
}

// ---------------------------------------------------------------
// gather2 + final: out[n] = (sum fp16 p[nb]) * dinv[n] + q[n]
// ---------------------------------------------------------------
__global__ void gather2_kernel(float* __restrict__ out) {
    int warp = (blockIdx.x * blockDim.x + threadIdx.x) >> 5;
    int lane = threadIdx.x & 31;
    if (warp >= N_NODES) return;
    int start = g_row[warp];
    int end = g_row[warp + 1];
    float a0 = 0.f, a1 = 0.f, a2 = 0.f, a3 = 0.f;
    for (int base = start; base < end; base += 32) {
        int mye = base + lane;
        int sidx = (mye < end) ? g_csrc[mye] : 0;
        int cnt = end - base; if (cnt > 32) cnt = 32;
#pragma unroll 4
        for (int j = 0; j < cnt; j++) {
            int s = __shfl_sync(0xffffffffu, sidx, j);
            uint2 v = __ldg((const uint2*)(g_p + (size_t)s * 128) + lane);
            float2 f0 = __half22float2(*reinterpret_cast<__half2*>(&v.x));
            float2 f1 = __half22float2(*reinterpret_cast<__half2*>(&v.y));
            a0 += f0.x; a1 += f0.y; a2 += f1.x; a3 += f1.y;
        }
    }
    float s = g_dinv[warp];
    uint2 qv = __ldg((const uint2*)(g_q + (size_t)warp * 128) + lane);
    float2 q0 = __half22float2(*reinterpret_cast<__half2*>(&qv.x));
    float2 q1 = __half22float2(*reinterpret_cast<__half2*>(&qv.y));
    float4 o;
    o.x = a0 * s + q0.x;
    o.y = a1 * s + q0.y;
    o.z = a2 * s + q1.x;
    o.w = a3 * s + q1.y;
    ((float4*)(out + (size_t)warp * 128))[lane] = o;
}

// ---------------------------------------------------------------
// mma.sync fp16 GEMM, 4-stage cp.async + ldmatrix. Single term, K=256.
// mode 1 (GEMM1): ReLU -> fp16 h (A2).
// mode 0 (GEMM2): n0=0 -> fp16 p; n0=128 -> fp16 q.
// ---------------------------------------------------------------
#define SSTR 40
#define NSTG 4
#define NCH 8

__global__ void __launch_bounds__(256, 2) gemm_mma_kernel(
    const uint4* __restrict__ A4, const uint4* __restrict__ W4,
    const float* __restrict__ bias,
    __half* __restrict__ outP, __half* __restrict__ outQ,
    unsigned* __restrict__ outH,
    int M, int mode) {
    __shared__ __align__(16) unsigned short As[NSTG][128 * SSTR];
    __shared__ __align__(16) unsigned short Bs[NSTG][128 * SSTR];
    __shared__ float bsm[128];

    int tid = threadIdx.x;
    int wid = tid >> 5, lane = tid & 31;
    int wy = wid & 3, wx = wid >> 2;
    int tig = lane & 3, grp = lane >> 2;
    int m0 = blockIdx.y * 128;
    int n0 = blockIdx.x * 128;

    if (tid < 128) bsm[tid] = bias[n0 + tid];

    float acc[2][8][4];
#pragma unroll
    for (int a = 0; a < 2; a++)
#pragma unroll
        for (int b = 0; b < 8; b++)
#pragma unroll
            for (int c = 0; c < 4; c++) acc[a][b][c] = 0.f;

    int lrow = tid >> 1;
    int lc0 = (tid & 1) * 2;
    int gmA = m0 + lrow; if (gmA >= M) gmA = M - 1;
    size_t aRow = (size_t)gmA * 32;
    size_t bRow = (size_t)(n0 + lrow) * 32;

#define ISSUE(ss) do {                                                         \
        int kb_ = (ss);                                                        \
        unsigned da = su32(&As[(ss) & (NSTG - 1)][lrow * SSTR + lc0 * 8]);     \
        unsigned db = su32(&Bs[(ss) & (NSTG - 1)][lrow * SSTR + lc0 * 8]);     \
        const uint4* sa = &A4[aRow + kb_ * 4 + lc0];                           \
        const uint4* sb = &W4[bRow + kb_ * 4 + lc0];                           \
        asm volatile("cp.async.cg.shared.global [%0], [%1], 16;" :: "r"(da), "l"(sa)); \
        asm volatile("cp.async.cg.shared.global [%0], [%1], 16;" :: "r"(da + 16), "l"(sa + 1)); \
        asm volatile("cp.async.cg.shared.global [%0], [%1], 16;" :: "r"(db), "l"(sb)); \
        asm volatile("cp.async.cg.shared.global [%0], [%1], 16;" :: "r"(db + 16), "l"(sb + 1)); \
        asm volatile("cp.async.commit_group;");                                \
    } while (0)

    ISSUE(0); ISSUE(1); ISSUE(2);

    int arow = wy * 32 + (lane & 15);
    int acol = (lane >> 4);
    int brow = wx * 64 + ((lane >> 4) & 1) * 8 + (lane & 7);
    int bcol = (lane >> 3) & 1;

    for (int c = 0; c < NCH; c++) {
        if (c <= NCH - 3)      asm volatile("cp.async.wait_group 2;");
        else if (c == NCH - 2) asm volatile("cp.async.wait_group 1;");
        else                   asm volatile("cp.async.wait_group 0;");
        __syncthreads();
        if (c + 3 < NCH) ISSUE(c + 3);

        int b = c & (NSTG - 1);
        const unsigned short* As_ = As[b];
        const unsigned short* Bs_ = Bs[b];
#pragma unroll
        for (int ks = 0; ks < 2; ks++) {
            unsigned af[2][4];
#pragma unroll
            for (int mt = 0; mt < 2; mt++) {
                unsigned addr = su32(&As_[(arow + mt * 16) * SSTR + (ks * 2 + acol) * 8]);
                asm volatile(
                    "ldmatrix.sync.aligned.m8n8.x4.shared.b16 {%0,%1,%2,%3}, [%4];"
                    : "=r"(af[mt][0]), "=r"(af[mt][1]), "=r"(af[mt][2]), "=r"(af[mt][3])
                    : "r"(addr));
            }
#pragma unroll
            for (int g = 0; g < 4; g++) {
                unsigned bf[4];
                unsigned addr = su32(&Bs_[(brow + g * 16) * SSTR + (ks * 2 + bcol) * 8]);
                asm volatile(
                    "ldmatrix.sync.aligned.m8n8.x4.shared.b16 {%0,%1,%2,%3}, [%4];"
                    : "=r"(bf[0]), "=r"(bf[1]), "=r"(bf[2]), "=r"(bf[3])
                    : "r"(addr));
#pragma unroll
                for (int mt = 0; mt < 2; mt++) {
                    asm volatile(
                        "mma.sync.aligned.m16n8k16.row.col.f32.f16.f16.f32 "
                        "{%0,%1,%2,%3}, {%4,%5,%6,%7}, {%8,%9}, {%0,%1,%2,%3};"
                        : "+f"(acc[mt][2 * g][0]), "+f"(acc[mt][2 * g][1]),
                          "+f"(acc[mt][2 * g][2]), "+f"(acc[mt][2 * g][3])
                        : "r"(af[mt][0]), "r"(af[mt][1]),
                          "r"(af[mt][2]), "r"(af[mt][3]),
                          "r"(bf[0]), "r"(bf[1]));
                    asm volatile(
                        "mma.sync.aligned.m16n8k16.row.col.f32.f16.f16.f32 "
                        "{%0,%1,%2,%3}, {%4,%5,%6,%7}, {%8,%9}, {%0,%1,%2,%3};"
                        : "+f"(acc[mt][2 * g + 1][0]), "+f"(acc[mt][2 * g + 1][1]),
                          "+f"(acc[mt][2 * g + 1][2]), "+f"(acc[mt][2 * g + 1][3])
                        : "r"(af[mt][0]), "r"(af[mt][1]),
                          "r"(af[mt][2]), "r"(af[mt][3]),
                          "r"(bf[2]), "r"(bf[3]));
                }
            }
        }
    }

    // epilogue
#pragma unroll
    for (int mt = 0; mt < 2; mt++) {
        int gm0 = m0 + wy * 32 + mt * 16 + grp;
#pragma unroll
        for (int nt = 0; nt < 8; nt++) {
            int nl = wx * 64 + nt * 8 + tig * 2;
            float bx = bsm[nl], by = bsm[nl + 1];
            float v0 = acc[mt][nt][0] + bx;
            float v1 = acc[mt][nt][1] + by;
            float v2 = acc[mt][nt][2] + bx;
            float v3 = acc[mt][nt][3] + by;
            if (mode == 1) {
                v0 = fmaxf(v0, 0.f); v1 = fmaxf(v1, 0.f);
                v2 = fmaxf(v2, 0.f); v3 = fmaxf(v3, 0.f);
                __half2 h01 = __floats2half2_rn(v0, v1);
                __half2 h23 = __floats2half2_rn(v2, v3);
                if (gm0 < M)
                    outH[(size_t)gm0 * 128 + (nl >> 1) + n0 / 2] =
                        *reinterpret_cast<unsigned*>(&h01);
                if (gm0 + 8 < M)
                    outH[(size_t)(gm0 + 8) * 128 + (nl >> 1) + n0 / 2] =
                        *reinterpret_cast<unsigned*>(&h23);
            } else {
                __half* dst = (n0 == 0) ? outP : outQ;
                if (gm0 < M)
                    *(__half2*)(dst + (size_t)gm0 * 128 + nl) = __floats2half2_rn(v0, v1);
                if (gm0 + 8 < M)
                    *(__half2*)(dst + (size_t)(gm0 + 8) * 128 + nl) = __floats2half2_rn(v2, v3);
            }
        }
    }
#undef ISSUE
}

// ---------------------------------------------------------------
// launch — inputs: x, Wl1, bl1, Wr1, Wl2, bl2, Wr2, edge_index
// ---------------------------------------------------------------
extern "C" void kernel_launch(void* const* d_in, const int* in_sizes, int n_in,
                              void* d_out, int out_size) {
    const float* x   = (const float*)d_in[0];
    const float* Wl1 = (const float*)d_in[1];
    const float* bl1 = (const float*)d_in[2];
    const float* Wr1 = (const float*)d_in[3];
    const float* Wl2 = (const float*)d_in[4];
    const float* bl2 = (const float*)d_in[5];
    const float* Wr2 = (const float*)d_in[6];
    const void*  ei  = d_in[7];
    float* out = (float*)d_out;

    unsigned *A1, *A2;
    unsigned short *W1, *W2;
    float *b1, *b2;
    __half *p, *q;
    cudaGetSymbolAddress((void**)&A1, g_A1);
    cudaGetSymbolAddress((void**)&A2, g_A2);
    cudaGetSymbolAddress((void**)&W1, g_W1);
    cudaGetSymbolAddress((void**)&W2, g_W2);
    cudaGetSymbolAddress((void**)&b1, g_b1);
    cudaGetSymbolAddress((void**)&b2, g_b2);
    cudaGetSymbolAddress((void**)&p, g_p);
    cudaGetSymbolAddress((void**)&q, g_q);

    // 0. init (degree zero + format probe), then vectorized degree count
    init_kernel<<<(N_NODES + 255) / 256, 256>>>((const int*)ei);
    deg_kernel<<<EDGE_NB, 256>>>(ei);

    // 1. CSR build (2-pass scan) + vectorized reorder
    scan_blocks_kernel<<<SCAN_NB, 256>>>();
    scan_finish_kernel<<<SCAN_NB, 256>>>();
    reorder_kernel<<<EDGE_NB, 256>>>(ei);

    // 2. fused prep: x fp16 + weights/biases
    {
        int items = XCONV_ITEMS + 2 * 256 * 256 + 512;
        prep_kernel<<<(items + 255) / 256, 256>>>(x, Wl1, Wr1, Wl2, Wr2, bl1, bl2);
    }

    // 3. layer-1 gather (fp16 x) -> A1 mean part
    gather1_kernel<<<(N_NODES + 7) / 8, 256>>>();

    // 4. GEMM1: h = relu([mean|x]@[Wl1|Wr1]ᵀ + b1) -> A2 fp16
    {
        dim3 grid(2, GEMM_MB);
        gemm_mma_kernel<<<grid, 256>>>((const uint4*)A1, (const uint4*)W1, b1,
                                       nullptr, nullptr, A2, N_NODES, 1);
    }

    // 5. GEMM2: p = h@Wl2ᵀ (fp16), q = h@Wr2ᵀ + bl2 (fp16)
    {
        dim3 grid(2, GEMM_MB);
        gemm_mma_kernel<<<grid, 256>>>((const uint4*)A2, (const uint4*)W2, b2,
                                       p, q, nullptr, N_NODES, 0);
    }

    // 6. layer-2 gather on fp16 p, fused with final combine
    gather2_kernel<<<(N_NODES + 7) / 8, 256>>>(out);
}